// round 15
// baseline (speedup 1.0000x reference)
#include <cuda_runtime.h>
#include <cuda_bf16.h>
#include <cstdint>

// Kohonen SOM pairwise L2 distance via bf16 mma.sync.m16n8k16.
//   out[b][n] = sqrt(max(||x_b||^2 + ||w_n||^2 - 2 x_b.w_n, 0))
// x [B=65536,32] f32, w [N=4900,32] f32, out [B,N] f32.
//
// R15 = R14 (prologue bf16-conversion + norms to globals; pure cp.async
// fill; 128x128 tile, 512 threads, 4x4 warp grid, sigma-placed B rows,
// pitch-20 conflict-free smem; permuted-column STG.128 epilogue) with
// latency/issue shaves:
//  (a) norm loads HOISTED ABOVE the mainloop (independent of it) so their
//      LDG latency overlaps MMA instead of stalling the store burst,
//  (b) uniform fast-path epilogue for interior n-tiles (38/39) — per-store
//      guards deleted on the hot path,
//  (c) store pointers precomputed once per thread (IMAD chains gone).

#define BM 128
#define BN 128
#define KD 32
#define PW 20        // b32 pitch per row (16 data + 4 pad); 80 B/row

__device__ float    g_x2[65536];
__device__ float    g_w2[8192];
__device__ unsigned g_xb[65536 * 16];   // bf16x2-packed x, 4 MB
__device__ unsigned g_wb[8192 * 16];    // bf16x2-packed w, 512 KB

__device__ __forceinline__ int sig16(int c) {
    return (((c >> 1) & 1) << 3) + ((c >> 2) << 1) + (c & 1);
}

__device__ __forceinline__ unsigned pack_bf16(float lo, float hi) {
    unsigned r;
    asm("cvt.rn.bf16x2.f32 %0, %1, %2;" : "=r"(r) : "f"(hi), "f"(lo));
    return r;
}

__device__ __forceinline__ float fsqrt_approx(float a) {
    float r;
    asm("sqrt.approx.f32 %0, %1;" : "=f"(r) : "f"(a));
    return r;
}

__device__ __forceinline__ unsigned smem_u32(const void* p) {
    unsigned a;
    asm("{ .reg .u64 t; cvta.to.shared.u64 t, %1; cvt.u32.u64 %0, t; }"
        : "=r"(a) : "l"(p));
    return a;
}

__device__ __forceinline__ void cp16(unsigned saddr, const void* gaddr) {
    asm volatile("cp.async.cg.shared.global [%0], [%1], 16;"
                 :: "r"(saddr), "l"(gaddr));
}
__device__ __forceinline__ void cp16_pred(unsigned saddr, const void* gaddr, int sz) {
    asm volatile("cp.async.cg.shared.global [%0], [%1], 16, %2;"
                 :: "r"(saddr), "l"(gaddr), "r"(sz));
}

__device__ __forceinline__ void mma_bf16(float* c, const unsigned* a, const unsigned* b) {
    asm volatile(
        "mma.sync.aligned.m16n8k16.row.col.f32.bf16.bf16.f32 "
        "{%0,%1,%2,%3}, {%4,%5,%6,%7}, {%8,%9}, {%0,%1,%2,%3};"
        : "+f"(c[0]), "+f"(c[1]), "+f"(c[2]), "+f"(c[3])
        : "r"(a[0]), "r"(a[1]), "r"(a[2]), "r"(a[3]),
          "r"(b[0]), "r"(b[1]));
}

// ---- prologue: norms + bf16 conversion ----
__global__ void prep_kernel(const float* __restrict__ x,
                            const float* __restrict__ w,
                            int B, int N) {
    int i = blockIdx.x * 256 + threadIdx.x;
    if (i < B) {
        const float4* s = (const float4*)(x + (size_t)i * KD);
        unsigned pk[16];
        float n = 0.f;
        #pragma unroll
        for (int q = 0; q < 8; ++q) {
            float4 v = s[q];
            n = fmaf(v.x, v.x, n); n = fmaf(v.y, v.y, n);
            n = fmaf(v.z, v.z, n); n = fmaf(v.w, v.w, n);
            pk[2 * q]     = pack_bf16(v.x, v.y);
            pk[2 * q + 1] = pack_bf16(v.z, v.w);
        }
        g_x2[i] = n;
        uint4* dst = (uint4*)&g_xb[i * 16];
        #pragma unroll
        for (int q = 0; q < 4; ++q)
            dst[q] = make_uint4(pk[4 * q], pk[4 * q + 1], pk[4 * q + 2], pk[4 * q + 3]);
    }
    if (i < N) {
        const float4* s = (const float4*)(w + (size_t)i * KD);
        unsigned pk[16];
        float n = 0.f;
        #pragma unroll
        for (int q = 0; q < 8; ++q) {
            float4 v = s[q];
            n = fmaf(v.x, v.x, n); n = fmaf(v.y, v.y, n);
            n = fmaf(v.z, v.z, n); n = fmaf(v.w, v.w, n);
            pk[2 * q]     = pack_bf16(v.x, v.y);
            pk[2 * q + 1] = pack_bf16(v.z, v.w);
        }
        g_w2[i] = n;
        uint4* dst = (uint4*)&g_wb[i * 16];
        #pragma unroll
        for (int q = 0; q < 4; ++q)
            dst[q] = make_uint4(pk[4 * q], pk[4 * q + 1], pk[4 * q + 2], pk[4 * q + 3]);
    }
}

__global__ __launch_bounds__(512, 2)
void som_mma_kernel(float* __restrict__ out, int B, int N) {
    __shared__ unsigned As[BM * PW];   // 10 KB
    __shared__ unsigned Bs[BN * PW];   // 10 KB (sigma-placed rows)

    const int tid    = threadIdx.x;
    const int m_base = blockIdx.y * BM;
    const int n_base = blockIdx.x * BN;

    // ---- fill: 1024 x 16B chunks via cp.async, 2 per thread ----
    {
        const unsigned as_base = smem_u32(As);
        const unsigned bs_base = smem_u32(Bs);
        #pragma unroll
        for (int p = 0; p < 2; ++p) {
            const int idx = tid + p * 512;     // 0..1023
            const int ch  = idx & 3;           // 16B chunk within row
            if (idx < 512) {
                const int row = idx >> 2;
                cp16(as_base + row * (PW * 4) + ch * 16,
                     (const char*)g_xb + ((size_t)(m_base + row) * 16 + ch * 4) * 4);
            } else {
                const int brow = (idx - 512) >> 2;
                const int srow = (brow & ~15) | sig16(brow & 15);
                const int gn   = n_base + brow;
                const int sz   = (gn < N) ? 16 : 0;   // 0 -> zero-fill, no read
                cp16_pred(bs_base + srow * (PW * 4) + ch * 16,
                          (const char*)g_wb + ((size_t)gn * 16 + ch * 4) * 4, sz);
            }
        }
        asm volatile("cp.async.commit_group;");
        asm volatile("cp.async.wait_group 0;");
    }

    // ---- warp coords ----
    const int lane   = tid & 31;
    const int wid    = tid >> 5;
    const int warp_m = (wid & 3) * 32;
    const int warp_n = (wid >> 2) * 32;
    const int qr     = lane >> 2;
    const int qc     = lane & 3;

    // ---- hoisted epilogue operands: norms + store pointers ----
    // indices provably in-bounds: m < B always; g_w2 is 8192 > 4991 max.
    const int r0g = m_base + warp_m + qr;
    const float x2_00 = __ldg(&g_x2[r0g]);          // tm=0, lo
    const float x2_01 = __ldg(&g_x2[r0g + 8]);      // tm=0, hi
    const float x2_10 = __ldg(&g_x2[r0g + 16]);     // tm=1, lo
    const float x2_11 = __ldg(&g_x2[r0g + 24]);     // tm=1, hi
    const int cg0 = n_base + warp_n + qc * 4;
    const float4 w2v0 = __ldg((const float4*)&g_w2[cg0]);        // i=0
    const float4 w2v1 = __ldg((const float4*)&g_w2[cg0 + 16]);   // i=1

    float* const st_base = out + (size_t)r0g * N + cg0;   // tm0-lo, i0
    const size_t stride8 = (size_t)8 * N;                 // rows +8

    __syncthreads();

    const unsigned* a_base = &As[(warp_m + qr) * PW + qc];
    const unsigned* b_base = &Bs[(warp_n + qr) * PW + qc];

    float acc[2][4][4];
    #pragma unroll
    for (int i = 0; i < 2; ++i)
        #pragma unroll
        for (int j = 0; j < 4; ++j)
            #pragma unroll
            for (int v = 0; v < 4; ++v) acc[i][j][v] = 0.f;

    #pragma unroll
    for (int ks = 0; ks < 2; ++ks) {
        const int o = ks * 8;                  // b32 offset of this k16 chunk

        unsigned af[2][4];
        #pragma unroll
        for (int tm = 0; tm < 2; ++tm) {
            const unsigned* r0 = a_base + tm * 16 * PW;
            af[tm][0] = r0[o];
            af[tm][1] = r0[8 * PW + o];
            af[tm][2] = r0[o + 4];
            af[tm][3] = r0[8 * PW + o + 4];
        }

        unsigned bf[4][2];
        #pragma unroll
        for (int tn = 0; tn < 4; ++tn) {
            const unsigned* c0 = b_base + ((tn >> 1) * 16 + (tn & 1) * 8) * PW;
            bf[tn][0] = c0[o];
            bf[tn][1] = c0[o + 4];
        }

        #pragma unroll
        for (int tm = 0; tm < 2; ++tm)
            #pragma unroll
            for (int tn = 0; tn < 4; ++tn)
                mma_bf16(acc[tm][tn], af[tm], bf[tn]);
    }

    // ---- epilogue ----
    const float x2_lo_[2] = { x2_00, x2_10 };
    const float x2_hi_[2] = { x2_01, x2_11 };
    const float4 w2_[2]   = { w2v0, w2v1 };
    const bool interior = (n_base + BN <= N);

    #pragma unroll
    for (int tm = 0; tm < 2; ++tm) {
        const float x2_lo = x2_lo_[tm];
        const float x2_hi = x2_hi_[tm];
        float* const p_lo = st_base + (size_t)(tm * 16) * N;   // row r0g+16tm
        float* const p_hi = p_lo + stride8;

        #pragma unroll
        for (int i = 0; i < 2; ++i) {
            const float4 w2v = w2_[i];
            const float* a0 = acc[tm][2 * i];
            const float* a1 = acc[tm][2 * i + 1];

            float4 lo, hi;
            lo.x = fsqrt_approx(fmaxf(fmaf(-2.f, a0[0], x2_lo + w2v.x), 0.f));
            lo.y = fsqrt_approx(fmaxf(fmaf(-2.f, a0[1], x2_lo + w2v.y), 0.f));
            lo.z = fsqrt_approx(fmaxf(fmaf(-2.f, a1[0], x2_lo + w2v.z), 0.f));
            lo.w = fsqrt_approx(fmaxf(fmaf(-2.f, a1[1], x2_lo + w2v.w), 0.f));
            hi.x = fsqrt_approx(fmaxf(fmaf(-2.f, a0[2], x2_hi + w2v.x), 0.f));
            hi.y = fsqrt_approx(fmaxf(fmaf(-2.f, a0[3], x2_hi + w2v.y), 0.f));
            hi.z = fsqrt_approx(fmaxf(fmaf(-2.f, a1[2], x2_hi + w2v.z), 0.f));
            hi.w = fsqrt_approx(fmaxf(fmaf(-2.f, a1[3], x2_hi + w2v.w), 0.f));

            if (interior) {
                __stcs((float4*)(p_lo + i * 16), lo);
                __stcs((float4*)(p_hi + i * 16), hi);
            } else {
                const int gn = cg0 + i * 16;
                if (gn < N) {                      // N%4==0 -> gn+3 valid
                    __stcs((float4*)(p_lo + i * 16), lo);
                    __stcs((float4*)(p_hi + i * 16), hi);
                }
            }
        }
    }
}

extern "C" void kernel_launch(void* const* d_in, const int* in_sizes, int n_in,
                              void* d_out, int out_size) {
    const float* x = (const float*)d_in[0];
    const float* w = (const float*)d_in[1];
    float* out     = (float*)d_out;

    int B = in_sizes[0] / KD;   // 65536
    int N = in_sizes[1] / KD;   // 4900

    prep_kernel<<<(B + 255) / 256, 256>>>(x, w, B, N);

    dim3 grid((N + BN - 1) / BN, (B + BM - 1) / BM);
    som_mma_kernel<<<grid, 512>>>(out, B, N);
}

// round 16
// speedup vs baseline: 1.0060x; 1.0060x over previous
#include <cuda_runtime.h>
#include <cuda_bf16.h>
#include <cstdint>

// Kohonen SOM pairwise L2 distance via bf16 mma.sync.m16n8k16.
//   out[b][n] = sqrt(max(||x_b||^2 + ||w_n||^2 - 2 x_b.w_n, 0))
// x [B=65536,32] f32, w [N=4900,32] f32, out [B,N] f32.
//
// R16 = R14 (prologue bf16-conversion + norms to globals; pure cp.async
// fill; 128x128 tile, 512 threads, 4x4 warp grid, sigma-placed B rows,
// pitch-20 conflict-free smem; permuted-column STG.128 epilogue) with ONLY
// the two epilogue shaves that R15 never isolated:
//  (b) uniform interior fast-path (38/39 n-tiles skip per-store guards),
//  (c) store pointers + norm loads batched ONCE at the top of the epilogue
//      (6-deep LDG MLP, one exposed stall instead of four; nothing held
//      live across the mainloop — R15's hoist (a) was the regression).

#define BM 128
#define BN 128
#define KD 32
#define PW 20        // b32 pitch per row (16 data + 4 pad); 80 B/row

__device__ float    g_x2[65536];
__device__ float    g_w2[8192];
__device__ unsigned g_xb[65536 * 16];   // bf16x2-packed x, 4 MB
__device__ unsigned g_wb[8192 * 16];    // bf16x2-packed w, 512 KB

__device__ __forceinline__ int sig16(int c) {
    return (((c >> 1) & 1) << 3) + ((c >> 2) << 1) + (c & 1);
}

__device__ __forceinline__ unsigned pack_bf16(float lo, float hi) {
    unsigned r;
    asm("cvt.rn.bf16x2.f32 %0, %1, %2;" : "=r"(r) : "f"(hi), "f"(lo));
    return r;
}

__device__ __forceinline__ float fsqrt_approx(float a) {
    float r;
    asm("sqrt.approx.f32 %0, %1;" : "=f"(r) : "f"(a));
    return r;
}

__device__ __forceinline__ unsigned smem_u32(const void* p) {
    unsigned a;
    asm("{ .reg .u64 t; cvta.to.shared.u64 t, %1; cvt.u32.u64 %0, t; }"
        : "=r"(a) : "l"(p));
    return a;
}

__device__ __forceinline__ void cp16(unsigned saddr, const void* gaddr) {
    asm volatile("cp.async.cg.shared.global [%0], [%1], 16;"
                 :: "r"(saddr), "l"(gaddr));
}
__device__ __forceinline__ void cp16_pred(unsigned saddr, const void* gaddr, int sz) {
    asm volatile("cp.async.cg.shared.global [%0], [%1], 16, %2;"
                 :: "r"(saddr), "l"(gaddr), "r"(sz));
}

__device__ __forceinline__ void mma_bf16(float* c, const unsigned* a, const unsigned* b) {
    asm volatile(
        "mma.sync.aligned.m16n8k16.row.col.f32.bf16.bf16.f32 "
        "{%0,%1,%2,%3}, {%4,%5,%6,%7}, {%8,%9}, {%0,%1,%2,%3};"
        : "+f"(c[0]), "+f"(c[1]), "+f"(c[2]), "+f"(c[3])
        : "r"(a[0]), "r"(a[1]), "r"(a[2]), "r"(a[3]),
          "r"(b[0]), "r"(b[1]));
}

// ---- prologue: norms + bf16 conversion ----
__global__ void prep_kernel(const float* __restrict__ x,
                            const float* __restrict__ w,
                            int B, int N) {
    int i = blockIdx.x * 256 + threadIdx.x;
    if (i < B) {
        const float4* s = (const float4*)(x + (size_t)i * KD);
        unsigned pk[16];
        float n = 0.f;
        #pragma unroll
        for (int q = 0; q < 8; ++q) {
            float4 v = s[q];
            n = fmaf(v.x, v.x, n); n = fmaf(v.y, v.y, n);
            n = fmaf(v.z, v.z, n); n = fmaf(v.w, v.w, n);
            pk[2 * q]     = pack_bf16(v.x, v.y);
            pk[2 * q + 1] = pack_bf16(v.z, v.w);
        }
        g_x2[i] = n;
        uint4* dst = (uint4*)&g_xb[i * 16];
        #pragma unroll
        for (int q = 0; q < 4; ++q)
            dst[q] = make_uint4(pk[4 * q], pk[4 * q + 1], pk[4 * q + 2], pk[4 * q + 3]);
    }
    if (i < N) {
        const float4* s = (const float4*)(w + (size_t)i * KD);
        unsigned pk[16];
        float n = 0.f;
        #pragma unroll
        for (int q = 0; q < 8; ++q) {
            float4 v = s[q];
            n = fmaf(v.x, v.x, n); n = fmaf(v.y, v.y, n);
            n = fmaf(v.z, v.z, n); n = fmaf(v.w, v.w, n);
            pk[2 * q]     = pack_bf16(v.x, v.y);
            pk[2 * q + 1] = pack_bf16(v.z, v.w);
        }
        g_w2[i] = n;
        uint4* dst = (uint4*)&g_wb[i * 16];
        #pragma unroll
        for (int q = 0; q < 4; ++q)
            dst[q] = make_uint4(pk[4 * q], pk[4 * q + 1], pk[4 * q + 2], pk[4 * q + 3]);
    }
}

__global__ __launch_bounds__(512, 2)
void som_mma_kernel(float* __restrict__ out, int B, int N) {
    __shared__ unsigned As[BM * PW];   // 10 KB
    __shared__ unsigned Bs[BN * PW];   // 10 KB (sigma-placed rows)

    const int tid    = threadIdx.x;
    const int m_base = blockIdx.y * BM;
    const int n_base = blockIdx.x * BN;

    // ---- fill: 1024 x 16B chunks via cp.async, 2 per thread ----
    {
        const unsigned as_base = smem_u32(As);
        const unsigned bs_base = smem_u32(Bs);
        #pragma unroll
        for (int p = 0; p < 2; ++p) {
            const int idx = tid + p * 512;     // 0..1023
            const int ch  = idx & 3;           // 16B chunk within row
            if (idx < 512) {
                const int row = idx >> 2;
                cp16(as_base + row * (PW * 4) + ch * 16,
                     (const char*)g_xb + ((size_t)(m_base + row) * 16 + ch * 4) * 4);
            } else {
                const int brow = (idx - 512) >> 2;
                const int srow = (brow & ~15) | sig16(brow & 15);
                const int gn   = n_base + brow;
                const int sz   = (gn < N) ? 16 : 0;   // 0 -> zero-fill, no read
                cp16_pred(bs_base + srow * (PW * 4) + ch * 16,
                          (const char*)g_wb + ((size_t)gn * 16 + ch * 4) * 4, sz);
            }
        }
        asm volatile("cp.async.commit_group;");
        asm volatile("cp.async.wait_group 0;");
    }
    __syncthreads();

    // ---- 4x4 warp grid, 32x32 warp tile, 2 k16 steps ----
    const int lane   = tid & 31;
    const int wid    = tid >> 5;
    const int warp_m = (wid & 3) * 32;
    const int warp_n = (wid >> 2) * 32;
    const int qr     = lane >> 2;
    const int qc     = lane & 3;

    const unsigned* a_base = &As[(warp_m + qr) * PW + qc];
    const unsigned* b_base = &Bs[(warp_n + qr) * PW + qc];

    float acc[2][4][4];
    #pragma unroll
    for (int i = 0; i < 2; ++i)
        #pragma unroll
        for (int j = 0; j < 4; ++j)
            #pragma unroll
            for (int v = 0; v < 4; ++v) acc[i][j][v] = 0.f;

    #pragma unroll
    for (int ks = 0; ks < 2; ++ks) {
        const int o = ks * 8;                  // b32 offset of this k16 chunk

        unsigned af[2][4];
        #pragma unroll
        for (int tm = 0; tm < 2; ++tm) {
            const unsigned* r0 = a_base + tm * 16 * PW;
            af[tm][0] = r0[o];
            af[tm][1] = r0[8 * PW + o];
            af[tm][2] = r0[o + 4];
            af[tm][3] = r0[8 * PW + o + 4];
        }

        unsigned bf[4][2];
        #pragma unroll
        for (int tn = 0; tn < 4; ++tn) {
            const unsigned* c0 = b_base + ((tn >> 1) * 16 + (tn & 1) * 8) * PW;
            bf[tn][0] = c0[o];
            bf[tn][1] = c0[o + 4];
        }

        #pragma unroll
        for (int tm = 0; tm < 2; ++tm)
            #pragma unroll
            for (int tn = 0; tn < 4; ++tn)
                mma_bf16(acc[tm][tn], af[tm], bf[tn]);
    }

    // ---- epilogue: batched norm loads + precomputed pointers ----
    // all 6 LDGs issue back-to-back here (MLP=6); nothing crossed the mainloop.
    const int r0g = m_base + warp_m + qr;
    const int cg0 = n_base + warp_n + qc * 4;
    const float x2_00 = __ldg(&g_x2[r0g]);
    const float x2_01 = __ldg(&g_x2[r0g + 8]);
    const float x2_10 = __ldg(&g_x2[r0g + 16]);
    const float x2_11 = __ldg(&g_x2[r0g + 24]);
    const float4 w2v0 = __ldg((const float4*)&g_w2[cg0]);        // i=0
    const float4 w2v1 = __ldg((const float4*)&g_w2[cg0 + 16]);   // i=1 (<=4991<8192)

    float* const st_base = out + (size_t)r0g * N + cg0;
    const size_t stride8 = (size_t)8 * N;

    const float  x2_lo_[2] = { x2_00, x2_10 };
    const float  x2_hi_[2] = { x2_01, x2_11 };
    const float4 w2_[2]    = { w2v0, w2v1 };
    const bool interior = (n_base + BN <= N);

    #pragma unroll
    for (int tm = 0; tm < 2; ++tm) {
        const float x2_lo = x2_lo_[tm];
        const float x2_hi = x2_hi_[tm];
        float* const p_lo = st_base + (size_t)(tm * 16) * N;
        float* const p_hi = p_lo + stride8;

        #pragma unroll
        for (int i = 0; i < 2; ++i) {
            const float4 w2v = w2_[i];
            const float* a0 = acc[tm][2 * i];
            const float* a1 = acc[tm][2 * i + 1];

            float4 lo, hi;
            lo.x = fsqrt_approx(fmaxf(fmaf(-2.f, a0[0], x2_lo + w2v.x), 0.f));
            lo.y = fsqrt_approx(fmaxf(fmaf(-2.f, a0[1], x2_lo + w2v.y), 0.f));
            lo.z = fsqrt_approx(fmaxf(fmaf(-2.f, a1[0], x2_lo + w2v.z), 0.f));
            lo.w = fsqrt_approx(fmaxf(fmaf(-2.f, a1[1], x2_lo + w2v.w), 0.f));
            hi.x = fsqrt_approx(fmaxf(fmaf(-2.f, a0[2], x2_hi + w2v.x), 0.f));
            hi.y = fsqrt_approx(fmaxf(fmaf(-2.f, a0[3], x2_hi + w2v.y), 0.f));
            hi.z = fsqrt_approx(fmaxf(fmaf(-2.f, a1[2], x2_hi + w2v.z), 0.f));
            hi.w = fsqrt_approx(fmaxf(fmaf(-2.f, a1[3], x2_hi + w2v.w), 0.f));

            if (interior) {
                __stcs((float4*)(p_lo + i * 16), lo);
                __stcs((float4*)(p_hi + i * 16), hi);
            } else {
                const int gn = cg0 + i * 16;
                if (gn < N) {                      // N%4==0 -> gn+3 valid
                    __stcs((float4*)(p_lo + i * 16), lo);
                    __stcs((float4*)(p_hi + i * 16), hi);
                }
            }
        }
    }
}

extern "C" void kernel_launch(void* const* d_in, const int* in_sizes, int n_in,
                              void* d_out, int out_size) {
    const float* x = (const float*)d_in[0];
    const float* w = (const float*)d_in[1];
    float* out     = (float*)d_out;

    int B = in_sizes[0] / KD;   // 65536
    int N = in_sizes[1] / KD;   // 4900

    prep_kernel<<<(B + 255) / 256, 256>>>(x, w, B, N);

    dim3 grid((N + BN - 1) / BN, (B + BM - 1) / BM);
    som_mma_kernel<<<grid, 512>>>(out, B, N);
}

// round 17
// speedup vs baseline: 1.1120x; 1.1054x over previous
#include <cuda_runtime.h>
#include <cuda_bf16.h>
#include <cstdint>

// Kohonen SOM pairwise L2 distance via bf16 mma.sync.m16n8k16.
//   out[b][n] = sqrt(max(||x_b||^2 + ||w_n||^2 - 2 x_b.w_n, 0))
// x [B=65536,32] f32, w [N=4900,32] f32, out [B,N] f32.
//
// R17 = R14 EXACTLY (prologue bf16+norms, cp.async fill, 128x128 tile,
// 512 threads, sigma-placed B rows, pitch-20 smem, R14's interleaved
// epilogue verbatim — R15/R16 proved both its order and its loads are
// locally optimal) + ONE change: each CTA processes TWO m-tiles sharing
// one B tile. The tile-1 A-fill (cp.async) is issued BEFORE the tile-0
// epilogue, so its ~600-cycle latency hides under ~2000 cycles of store
// work. Halves exposed fill stalls and B-tile traffic; grid y halves.

#define BM 128
#define BN 128
#define KD 32
#define PW 20        // b32 pitch per row (16 data + 4 pad); 80 B/row

__device__ float    g_x2[65536];
__device__ float    g_w2[8192];
__device__ unsigned g_xb[65536 * 16];   // bf16x2-packed x, 4 MB
__device__ unsigned g_wb[8192 * 16];    // bf16x2-packed w, 512 KB

__device__ __forceinline__ int sig16(int c) {
    return (((c >> 1) & 1) << 3) + ((c >> 2) << 1) + (c & 1);
}

__device__ __forceinline__ unsigned pack_bf16(float lo, float hi) {
    unsigned r;
    asm("cvt.rn.bf16x2.f32 %0, %1, %2;" : "=r"(r) : "f"(hi), "f"(lo));
    return r;
}

__device__ __forceinline__ float fsqrt_approx(float a) {
    float r;
    asm("sqrt.approx.f32 %0, %1;" : "=f"(r) : "f"(a));
    return r;
}

__device__ __forceinline__ unsigned smem_u32(const void* p) {
    unsigned a;
    asm("{ .reg .u64 t; cvta.to.shared.u64 t, %1; cvt.u32.u64 %0, t; }"
        : "=r"(a) : "l"(p));
    return a;
}

__device__ __forceinline__ void cp16(unsigned saddr, const void* gaddr) {
    asm volatile("cp.async.cg.shared.global [%0], [%1], 16;"
                 :: "r"(saddr), "l"(gaddr));
}
__device__ __forceinline__ void cp16_pred(unsigned saddr, const void* gaddr, int sz) {
    asm volatile("cp.async.cg.shared.global [%0], [%1], 16, %2;"
                 :: "r"(saddr), "l"(gaddr), "r"(sz));
}

__device__ __forceinline__ void mma_bf16(float* c, const unsigned* a, const unsigned* b) {
    asm volatile(
        "mma.sync.aligned.m16n8k16.row.col.f32.bf16.bf16.f32 "
        "{%0,%1,%2,%3}, {%4,%5,%6,%7}, {%8,%9}, {%0,%1,%2,%3};"
        : "+f"(c[0]), "+f"(c[1]), "+f"(c[2]), "+f"(c[3])
        : "r"(a[0]), "r"(a[1]), "r"(a[2]), "r"(a[3]),
          "r"(b[0]), "r"(b[1]));
}

// ---- prologue: norms + bf16 conversion ----
__global__ void prep_kernel(const float* __restrict__ x,
                            const float* __restrict__ w,
                            int B, int N) {
    int i = blockIdx.x * 256 + threadIdx.x;
    if (i < B) {
        const float4* s = (const float4*)(x + (size_t)i * KD);
        unsigned pk[16];
        float n = 0.f;
        #pragma unroll
        for (int q = 0; q < 8; ++q) {
            float4 v = s[q];
            n = fmaf(v.x, v.x, n); n = fmaf(v.y, v.y, n);
            n = fmaf(v.z, v.z, n); n = fmaf(v.w, v.w, n);
            pk[2 * q]     = pack_bf16(v.x, v.y);
            pk[2 * q + 1] = pack_bf16(v.z, v.w);
        }
        g_x2[i] = n;
        uint4* dst = (uint4*)&g_xb[i * 16];
        #pragma unroll
        for (int q = 0; q < 4; ++q)
            dst[q] = make_uint4(pk[4 * q], pk[4 * q + 1], pk[4 * q + 2], pk[4 * q + 3]);
    }
    if (i < N) {
        const float4* s = (const float4*)(w + (size_t)i * KD);
        unsigned pk[16];
        float n = 0.f;
        #pragma unroll
        for (int q = 0; q < 8; ++q) {
            float4 v = s[q];
            n = fmaf(v.x, v.x, n); n = fmaf(v.y, v.y, n);
            n = fmaf(v.z, v.z, n); n = fmaf(v.w, v.w, n);
            pk[2 * q]     = pack_bf16(v.x, v.y);
            pk[2 * q + 1] = pack_bf16(v.z, v.w);
        }
        g_w2[i] = n;
        uint4* dst = (uint4*)&g_wb[i * 16];
        #pragma unroll
        for (int q = 0; q < 4; ++q)
            dst[q] = make_uint4(pk[4 * q], pk[4 * q + 1], pk[4 * q + 2], pk[4 * q + 3]);
    }
}

// ---- R14 mainloop over one A buffer ----
__device__ __forceinline__ void run_mainloop(const unsigned* __restrict__ As,
                                             const unsigned* __restrict__ Bs,
                                             int warp_m, int warp_n,
                                             int qr, int qc,
                                             float acc[2][4][4]) {
    #pragma unroll
    for (int i = 0; i < 2; ++i)
        #pragma unroll
        for (int j = 0; j < 4; ++j)
            #pragma unroll
            for (int v = 0; v < 4; ++v) acc[i][j][v] = 0.f;

    const unsigned* a_base = &As[(warp_m + qr) * PW + qc];
    const unsigned* b_base = &Bs[(warp_n + qr) * PW + qc];

    #pragma unroll
    for (int ks = 0; ks < 2; ++ks) {
        const int o = ks * 8;

        unsigned af[2][4];
        #pragma unroll
        for (int tm = 0; tm < 2; ++tm) {
            const unsigned* r0 = a_base + tm * 16 * PW;
            af[tm][0] = r0[o];
            af[tm][1] = r0[8 * PW + o];
            af[tm][2] = r0[o + 4];
            af[tm][3] = r0[8 * PW + o + 4];
        }

        unsigned bf[4][2];
        #pragma unroll
        for (int tn = 0; tn < 4; ++tn) {
            const unsigned* c0 = b_base + ((tn >> 1) * 16 + (tn & 1) * 8) * PW;
            bf[tn][0] = c0[o];
            bf[tn][1] = c0[o + 4];
        }

        #pragma unroll
        for (int tm = 0; tm < 2; ++tm)
            #pragma unroll
            for (int tn = 0; tn < 4; ++tn)
                mma_bf16(acc[tm][tn], af[tm], bf[tn]);
    }
}

// ---- R14 epilogue, verbatim structure (interleaved loads + guards) ----
__device__ __forceinline__ void run_epilogue(float* __restrict__ out,
                                             const float acc[2][4][4],
                                             int m_base, int n_base,
                                             int warp_m, int warp_n,
                                             int qr, int qc, int N) {
    #pragma unroll
    for (int tm = 0; tm < 2; ++tm) {
        const int r_lo = warp_m + tm * 16 + qr;
        const float x2_lo = __ldg(&g_x2[m_base + r_lo]);
        const float x2_hi = __ldg(&g_x2[m_base + r_lo + 8]);
        const size_t off_lo = (size_t)(m_base + r_lo) * N;
        const size_t off_hi = off_lo + (size_t)8 * N;

        #pragma unroll
        for (int i = 0; i < 2; ++i) {
            const int c  = warp_n + qc * 4 + i * 16;
            const int gn = n_base + c;
            if (gn < N) {
                const float4 w2v = __ldg((const float4*)&g_w2[gn]);
                const float* a0 = acc[tm][2 * i];
                const float* a1 = acc[tm][2 * i + 1];

                float4 lo, hi;
                lo.x = fsqrt_approx(fmaxf(fmaf(-2.f, a0[0], x2_lo + w2v.x), 0.f));
                lo.y = fsqrt_approx(fmaxf(fmaf(-2.f, a0[1], x2_lo + w2v.y), 0.f));
                lo.z = fsqrt_approx(fmaxf(fmaf(-2.f, a1[0], x2_lo + w2v.z), 0.f));
                lo.w = fsqrt_approx(fmaxf(fmaf(-2.f, a1[1], x2_lo + w2v.w), 0.f));
                hi.x = fsqrt_approx(fmaxf(fmaf(-2.f, a0[2], x2_hi + w2v.x), 0.f));
                hi.y = fsqrt_approx(fmaxf(fmaf(-2.f, a0[3], x2_hi + w2v.y), 0.f));
                hi.z = fsqrt_approx(fmaxf(fmaf(-2.f, a1[2], x2_hi + w2v.z), 0.f));
                hi.w = fsqrt_approx(fmaxf(fmaf(-2.f, a1[3], x2_hi + w2v.w), 0.f));

                __stcs((float4*)(out + off_lo + gn), lo);
                __stcs((float4*)(out + off_hi + gn), hi);
            }
        }
    }
}

__global__ __launch_bounds__(512, 2)
void som_mma_kernel(float* __restrict__ out, int B, int N) {
    __shared__ unsigned As0[BM * PW];  // 10 KB
    __shared__ unsigned As1[BM * PW];  // 10 KB (prefetched tile-1 A)
    __shared__ unsigned Bs[BN * PW];   // 10 KB (sigma-placed rows, shared)

    const int tid     = threadIdx.x;
    const int m_base0 = blockIdx.y * (2 * BM);
    const int m_base1 = m_base0 + BM;
    const int n_base  = blockIdx.x * BN;

    const unsigned as0_base = smem_u32(As0);
    const unsigned as1_base = smem_u32(As1);
    const unsigned bs_base  = smem_u32(Bs);

    // ---- fill tile-0 A + shared B: 1024 chunks, R14 pattern ----
    #pragma unroll
    for (int p = 0; p < 2; ++p) {
        const int idx = tid + p * 512;
        const int ch  = idx & 3;
        if (idx < 512) {
            const int row = idx >> 2;
            cp16(as0_base + row * (PW * 4) + ch * 16,
                 (const char*)g_xb + ((size_t)(m_base0 + row) * 16 + ch * 4) * 4);
        } else {
            const int brow = (idx - 512) >> 2;
            const int srow = (brow & ~15) | sig16(brow & 15);
            const int gn   = n_base + brow;
            const int sz   = (gn < N) ? 16 : 0;
            cp16_pred(bs_base + srow * (PW * 4) + ch * 16,
                      (const char*)g_wb + ((size_t)gn * 16 + ch * 4) * 4, sz);
        }
    }
    asm volatile("cp.async.commit_group;");
    asm volatile("cp.async.wait_group 0;");
    __syncthreads();

    const int lane   = tid & 31;
    const int wid    = tid >> 5;
    const int warp_m = (wid & 3) * 32;
    const int warp_n = (wid >> 2) * 32;
    const int qr     = lane >> 2;
    const int qc     = lane & 3;

    float acc[2][4][4];

    // ---- tile 0: mainloop ----
    run_mainloop(As0, Bs, warp_m, warp_n, qr, qc, acc);

    // ---- prefetch tile-1 A (hides under tile-0 epilogue) ----
    {
        const int row = tid >> 2;
        const int ch  = tid & 3;
        cp16(as1_base + row * (PW * 4) + ch * 16,
             (const char*)g_xb + ((size_t)(m_base1 + row) * 16 + ch * 4) * 4);
        asm volatile("cp.async.commit_group;");
    }

    // ---- tile 0: epilogue (R14 verbatim) ----
    run_epilogue(out, acc, m_base0, n_base, warp_m, warp_n, qr, qc, N);

    // ---- tile 1 ----
    asm volatile("cp.async.wait_group 0;");
    __syncthreads();

    run_mainloop(As1, Bs, warp_m, warp_n, qr, qc, acc);
    run_epilogue(out, acc, m_base1, n_base, warp_m, warp_n, qr, qc, N);
}

extern "C" void kernel_launch(void* const* d_in, const int* in_sizes, int n_in,
                              void* d_out, int out_size) {
    const float* x = (const float*)d_in[0];
    const float* w = (const float*)d_in[1];
    float* out     = (float*)d_out;

    int B = in_sizes[0] / KD;   // 65536
    int N = in_sizes[1] / KD;   // 4900

    prep_kernel<<<(B + 255) / 256, 256>>>(x, w, B, N);

    dim3 grid((N + BN - 1) / BN, B / (2 * BM));   // (39, 256)
    som_mma_kernel<<<grid, 512>>>(out, B, N);
}